// round 8
// baseline (speedup 1.0000x reference)
#include <cuda_runtime.h>
#include <cstdint>

// s=2048, nh=16, hs=64, fp32. b from in_sizes.
#define NHD   16
#define HSZ   64
#define BR    64
#define BC    64
#define KSTR  72   // K smem stride: LDS.64 K-frags bank = (8g+2tg) -> conflict-free
#define VSTR  68   // V smem stride: LDS.32 V-frags bank = (8tg+4d+8nt+g) -> conflict-free
#define SM_K  (2 * 64 * KSTR)
#define SM_V  (2 * 64 * VSTR)
#define SMEM_BYTES ((SM_K + SM_V) * 4)   // 70 KB -> 3 CTAs/SM
#define NEGBIG (-1e30f)
#define LOG2E  1.4426950408889634f

__device__ __forceinline__ uint32_t f2tf(float x) {
    uint32_t r;
    asm("cvt.rna.tf32.f32 %0, %1;" : "=r"(r) : "f"(x));
    return r;
}
__device__ __forceinline__ float ex2(float x) {
    float y;
    asm("ex2.approx.f32 %0, %1;" : "=f"(y) : "f"(x));
    return y;
}
__device__ __forceinline__ void mma8(float* d,
                                     uint32_t a0, uint32_t a1, uint32_t a2, uint32_t a3,
                                     uint32_t b0, uint32_t b1) {
    asm volatile(
        "mma.sync.aligned.m16n8k8.row.col.f32.tf32.tf32.f32 "
        "{%0,%1,%2,%3},{%4,%5,%6,%7},{%8,%9},{%0,%1,%2,%3};"
        : "+f"(d[0]), "+f"(d[1]), "+f"(d[2]), "+f"(d[3])
        : "r"(a0), "r"(a1), "r"(a2), "r"(a3), "r"(b0), "r"(b1));
}
__device__ __forceinline__ void cpa16(uint32_t dst, const void* src) {
    asm volatile("cp.async.cg.shared.global [%0], [%1], 16;" :: "r"(dst), "l"(src));
}

// k-permutation sigma(tg)=2tg, sigma(tg+4)=2tg+1 applied consistently to
// (Q,K) for S=QK^T and to (P,V) for O=PV. Under sigma, the S accumulator
// C-fragment (c0,c2,c1,c3) IS the A-fragment of P -> no SMEM repack.
// K is pre-converted to tf32 (rna) in SMEM once per tile, so mainloop feeds
// raw bits to the MMA (hardware truncation of already-rounded bits == rna).
__global__ void __launch_bounds__(128, 3) fa_glm_kernel(
    const float* __restrict__ q, const float* __restrict__ k,
    const float* __restrict__ v, const int* __restrict__ glm,
    float* __restrict__ out, int seq)
{
    extern __shared__ float sm[];
    float* Ks0 = sm;
    float* Vs0 = sm + SM_K;

    // Heavy q-tiles (large qt => more KV tiles) first: better last-wave tail.
    const int qt = gridDim.x - 1 - blockIdx.x;
    const int h = blockIdx.y, bi = blockIdx.z;
    const int tid = threadIdx.x, lane = tid & 31, w = tid >> 5;
    const int g = lane >> 2, tg = lane & 3;

    const int bp   = glm[bi];
    const int iq0  = qt * BR;
    const int kend = max(iq0 + BR, bp);
    const int KT   = (kend + BC - 1) / BC;

    const size_t rs = (size_t)NHD * HSZ;
    const float* qb = q + (size_t)bi * seq * rs + (size_t)h * HSZ;
    const float* kb = k + (size_t)bi * seq * rs + (size_t)h * HSZ;
    const float* vb = v + (size_t)bi * seq * rs + (size_t)h * HSZ;
    float*       ob = out + (size_t)bi * seq * rs + (size_t)h * HSZ;

    auto issue_kv = [&](int kt, int buf) {
        if (kt < KT) {
            const float* sk = kb + (size_t)(kt * BC) * rs;
            const float* sv = vb + (size_t)(kt * BC) * rs;
            uint32_t kd = (uint32_t)__cvta_generic_to_shared(Ks0 + buf * 64 * KSTR);
            uint32_t vd = (uint32_t)__cvta_generic_to_shared(Vs0 + buf * 64 * VSTR);
            #pragma unroll
            for (int it = 0; it < 8; it++) {
                int c = tid + it * 128;
                int r = c >> 4, p = (c & 15) * 4;
                cpa16(kd + (r * KSTR + p) * 4, sk + (size_t)r * rs + p);
                cpa16(vd + (r * VSTR + p) * 4, sv + (size_t)r * rs + p);
            }
        }
        asm volatile("cp.async.commit_group;");
    };
    issue_kv(0, 0);
    issue_kv(1, 1);

    const int r_lo = iq0 + w * 16 + g;
    const int r_hi = r_lo + 8;

    // --- Q fragments straight from GMEM (permuted k, scale = log2e/8) ---
    uint32_t qa[8][4];
    {
        const float qs = 0.125f * LOG2E;
        const float* q0 = qb + (size_t)r_lo * rs + 2 * tg;
        const float* q1 = qb + (size_t)r_hi * rs + 2 * tg;
        #pragma unroll
        for (int ks = 0; ks < 8; ks++) {
            float2 x0 = *(const float2*)(q0 + ks * 8);
            float2 x1 = *(const float2*)(q1 + ks * 8);
            qa[ks][0] = f2tf(x0.x * qs); qa[ks][2] = f2tf(x0.y * qs);
            qa[ks][1] = f2tf(x1.x * qs); qa[ks][3] = f2tf(x1.y * qs);
        }
    }

    float O[8][4];
    #pragma unroll
    for (int i = 0; i < 8; i++) { O[i][0] = O[i][1] = O[i][2] = O[i][3] = 0.f; }
    float m0 = NEGBIG, m1 = NEGBIG, l0 = 0.f, l1 = 0.f;

    for (int kt = 0; kt < KT; kt++) {
        const int buf = kt & 1;
        asm volatile("cp.async.wait_group 1;");
        __syncthreads();

        float* Kb = Ks0 + buf * 64 * KSTR;
        const float* Vb = Vs0 + buf * 64 * VSTR;

        // --- pre-convert K tile to tf32(rna) in place (whole CTA) ---
        #pragma unroll
        for (int it = 0; it < 8; it++) {
            int c = tid + it * 128;
            int r = c >> 4, p = (c & 15) * 4;
            float4* a = (float4*)(Kb + r * KSTR + p);
            float4 x = *a;
            uint4 y;
            y.x = f2tf(x.x); y.y = f2tf(x.y); y.z = f2tf(x.z); y.w = f2tf(x.w);
            *(uint4*)a = y;
        }
        __syncthreads();

        // --- S = (Q*log2e/8) K^T  (LDS.64 raw-bit K frags, permuted k) ---
        float S[8][4];
        #pragma unroll
        for (int i = 0; i < 8; i++) { S[i][0] = S[i][1] = S[i][2] = S[i][3] = 0.f; }
        #pragma unroll
        for (int ks = 0; ks < 8; ks++) {
            #pragma unroll
            for (int nt = 0; nt < 8; nt++) {
                uint2 kk = *(const uint2*)(Kb + (nt * 8 + g) * KSTR + ks * 8 + 2 * tg);
                mma8(S[nt], qa[ks][0], qa[ks][1], qa[ks][2], qa[ks][3],
                     kk.x, kk.y);
            }
        }

        // --- GLM mask: allowed iff (j <= i) || (j < bp) ---
        const bool needmask = (kt >= qt) && ((kt + 1) * BC > bp);
        if (needmask) {
            #pragma unroll
            for (int nt = 0; nt < 8; nt++) {
                int j0 = kt * BC + nt * 8 + tg * 2;
                if (!(j0     <= r_lo || j0     < bp)) S[nt][0] = NEGBIG;
                if (!(j0 + 1 <= r_lo || j0 + 1 < bp)) S[nt][1] = NEGBIG;
                if (!(j0     <= r_hi || j0     < bp)) S[nt][2] = NEGBIG;
                if (!(j0 + 1 <= r_hi || j0 + 1 < bp)) S[nt][3] = NEGBIG;
            }
        }

        // --- online softmax in exp2 domain (rows owned by lane quads) ---
        float t0 = NEGBIG, t1 = NEGBIG;
        #pragma unroll
        for (int nt = 0; nt < 8; nt++) {
            t0 = fmaxf(t0, fmaxf(S[nt][0], S[nt][1]));
            t1 = fmaxf(t1, fmaxf(S[nt][2], S[nt][3]));
        }
        t0 = fmaxf(t0, __shfl_xor_sync(0xffffffffu, t0, 1));
        t0 = fmaxf(t0, __shfl_xor_sync(0xffffffffu, t0, 2));
        t1 = fmaxf(t1, __shfl_xor_sync(0xffffffffu, t1, 1));
        t1 = fmaxf(t1, __shfl_xor_sync(0xffffffffu, t1, 2));
        const float mn0 = fmaxf(m0, t0), mn1 = fmaxf(m1, t1);
        const float rsc0 = ex2(m0 - mn0), rsc1 = ex2(m1 - mn1);
        m0 = mn0; m1 = mn1;
        float sum0 = 0.f, sum1 = 0.f;
        #pragma unroll
        for (int nt = 0; nt < 8; nt++) {
            S[nt][0] = ex2(S[nt][0] - mn0);
            S[nt][1] = ex2(S[nt][1] - mn0);
            S[nt][2] = ex2(S[nt][2] - mn1);
            S[nt][3] = ex2(S[nt][3] - mn1);
            sum0 += S[nt][0] + S[nt][1];
            sum1 += S[nt][2] + S[nt][3];
            O[nt][0] *= rsc0; O[nt][1] *= rsc0;
            O[nt][2] *= rsc1; O[nt][3] *= rsc1;
        }
        sum0 += __shfl_xor_sync(0xffffffffu, sum0, 1);
        sum0 += __shfl_xor_sync(0xffffffffu, sum0, 2);
        sum1 += __shfl_xor_sync(0xffffffffu, sum1, 1);
        sum1 += __shfl_xor_sync(0xffffffffu, sum1, 2);
        l0 = l0 * rsc0 + sum0;
        l1 = l1 * rsc1 + sum1;

        // --- O += P V : S C-frag (c0,c2,c1,c3) == P A-frag under sigma ---
        #pragma unroll
        for (int ks = 0; ks < 8; ks++) {
            uint32_t a0 = f2tf(S[ks][0]);
            uint32_t a1 = f2tf(S[ks][2]);
            uint32_t a2 = f2tf(S[ks][1]);
            uint32_t a3 = f2tf(S[ks][3]);
            const float* v0 = Vb + (ks * 8 + 2 * tg) * VSTR + g;
            #pragma unroll
            for (int nt = 0; nt < 8; nt++) {
                uint32_t b0 = __float_as_uint(v0[nt * 8]);
                uint32_t b1 = __float_as_uint(v0[VSTR + nt * 8]);
                mma8(O[nt], a0, a1, a2, a3, b0, b1);
            }
        }

        __syncthreads();              // all warps done with this KV buffer
        issue_kv(kt + 2, buf);        // (empty commit past KT keeps groups aligned)
    }
    asm volatile("cp.async.wait_group 0;");

    // --- normalize + store ---
    const float inv0 = 1.f / l0, inv1 = 1.f / l1;
    #pragma unroll
    for (int nt = 0; nt < 8; nt++) {
        const int d = nt * 8 + tg * 2;
        *(float2*)(ob + (size_t)r_lo * rs + d) = make_float2(O[nt][0] * inv0, O[nt][1] * inv0);
        *(float2*)(ob + (size_t)r_hi * rs + d) = make_float2(O[nt][2] * inv1, O[nt][3] * inv1);
    }
}

extern "C" void kernel_launch(void* const* d_in, const int* in_sizes, int n_in,
                              void* d_out, int out_size) {
    const float* q   = (const float*)d_in[0];
    const float* k   = (const float*)d_in[1];
    const float* v   = (const float*)d_in[2];
    const int*   glm = (const int*)d_in[3];
    const int b   = in_sizes[3];
    const int seq = in_sizes[0] / (b * NHD * HSZ);

    cudaFuncSetAttribute(fa_glm_kernel,
                         cudaFuncAttributeMaxDynamicSharedMemorySize, SMEM_BYTES);
    dim3 grid(seq / BR, NHD, b);
    fa_glm_kernel<<<grid, 128, SMEM_BYTES>>>(q, k, v, glm, (float*)d_out, seq);
}

// round 10
// speedup vs baseline: 1.0174x; 1.0174x over previous
#include <cuda_runtime.h>
#include <cstdint>

// s=2048, nh=16, hs=64, fp32. b from in_sizes.
#define NHD   16
#define HSZ   64
#define BR    64
#define BC    64
#define KSTR  72   // K smem stride: LDS.64 K-frags bank = (8g+2tg) -> conflict-free
#define VSTR  68   // V smem stride: LDS.32 V-frags bank = (8tg+4d+8nt+g) -> conflict-free
#define SM_K  (2 * 64 * KSTR)
#define SM_V  (2 * 64 * VSTR)
#define SMEM_BYTES ((SM_K + SM_V) * 4)   // 70 KB -> 3 CTAs/SM
#define NEGBIG (-1e30f)
#define LOG2E  1.4426950408889634f

__device__ __forceinline__ uint32_t f2tf(float x) {
    uint32_t r;
    asm("cvt.rna.tf32.f32 %0, %1;" : "=r"(r) : "f"(x));
    return r;
}
__device__ __forceinline__ float ex2(float x) {
    float y;
    asm("ex2.approx.f32 %0, %1;" : "=f"(y) : "f"(x));
    return y;
}
__device__ __forceinline__ void mma8(float* d,
                                     uint32_t a0, uint32_t a1, uint32_t a2, uint32_t a3,
                                     uint32_t b0, uint32_t b1) {
    asm volatile(
        "mma.sync.aligned.m16n8k8.row.col.f32.tf32.tf32.f32 "
        "{%0,%1,%2,%3},{%4,%5,%6,%7},{%8,%9},{%0,%1,%2,%3};"
        : "+f"(d[0]), "+f"(d[1]), "+f"(d[2]), "+f"(d[3])
        : "r"(a0), "r"(a1), "r"(a2), "r"(a3), "r"(b0), "r"(b1));
}
__device__ __forceinline__ void cpa16(uint32_t dst, const void* src) {
    asm volatile("cp.async.cg.shared.global [%0], [%1], 16;" :: "r"(dst), "l"(src));
}

// k-permutation sigma(tg)=2tg, sigma(tg+4)=2tg+1 applied consistently to
// (Q,K) for S=QK^T and to (P,V) for O=PV. Under sigma, the S accumulator
// C-fragment (c0,c2,c1,c3) IS the A-fragment of P -> no SMEM repack.
// Each 64-wide KV tile is processed as two 32-col halves with the S-MMAs of
// half B emitted inside softmax-A's dependency chain (and softmax-B inside
// PV-A) so ptxas can fill SHFL/MUFU/HMMA latency with independent work.
__global__ void __launch_bounds__(128, 3) fa_glm_kernel(
    const float* __restrict__ q, const float* __restrict__ k,
    const float* __restrict__ v, const int* __restrict__ glm,
    float* __restrict__ out, int seq)
{
    extern __shared__ float sm[];
    float* Ks0 = sm;
    float* Vs0 = sm + SM_K;

    // Heavy q-tiles (large qt => more KV tiles) first: better last-wave tail.
    const int qt = gridDim.x - 1 - blockIdx.x;
    const int h = blockIdx.y, bi = blockIdx.z;
    const int tid = threadIdx.x, lane = tid & 31, w = tid >> 5;
    const int g = lane >> 2, tg = lane & 3;

    const int bp   = glm[bi];
    const int iq0  = qt * BR;
    const int kend = max(iq0 + BR, bp);
    const int KT   = (kend + BC - 1) / BC;

    const size_t rs = (size_t)NHD * HSZ;
    const float* qb = q + (size_t)bi * seq * rs + (size_t)h * HSZ;
    const float* kb = k + (size_t)bi * seq * rs + (size_t)h * HSZ;
    const float* vb = v + (size_t)bi * seq * rs + (size_t)h * HSZ;
    float*       ob = out + (size_t)bi * seq * rs + (size_t)h * HSZ;

    auto issue_kv = [&](int t, int buf) {
        if (t < KT) {
            const float* sk = kb + (size_t)(t * BC) * rs;
            const float* sv = vb + (size_t)(t * BC) * rs;
            uint32_t kd = (uint32_t)__cvta_generic_to_shared(Ks0 + buf * 64 * KSTR);
            uint32_t vd = (uint32_t)__cvta_generic_to_shared(Vs0 + buf * 64 * VSTR);
            #pragma unroll
            for (int it = 0; it < 8; it++) {
                int c = tid + it * 128;
                int r = c >> 4, p = (c & 15) * 4;
                cpa16(kd + (r * KSTR + p) * 4, sk + (size_t)r * rs + p);
                cpa16(vd + (r * VSTR + p) * 4, sv + (size_t)r * rs + p);
            }
        }
        asm volatile("cp.async.commit_group;");
    };
    issue_kv(0, 0);
    issue_kv(1, 1);

    const int r_lo = iq0 + w * 16 + g;
    const int r_hi = r_lo + 8;

    // --- Q fragments straight from GMEM (permuted k, scale = log2e/8) ---
    uint32_t qa[8][4];
    {
        const float qs = 0.125f * LOG2E;
        const float* q0 = qb + (size_t)r_lo * rs + 2 * tg;
        const float* q1 = qb + (size_t)r_hi * rs + 2 * tg;
        #pragma unroll
        for (int ks = 0; ks < 8; ks++) {
            float2 x0 = *(const float2*)(q0 + ks * 8);
            float2 x1 = *(const float2*)(q1 + ks * 8);
            qa[ks][0] = f2tf(x0.x * qs); qa[ks][2] = f2tf(x0.y * qs);
            qa[ks][1] = f2tf(x1.x * qs); qa[ks][3] = f2tf(x1.y * qs);
        }
    }

    float O[8][4];
    #pragma unroll
    for (int i = 0; i < 8; i++) { O[i][0] = O[i][1] = O[i][2] = O[i][3] = 0.f; }
    float m = NEGBIG, l = 0.f;   // shared row state (lo in m/l via lane pairs)
    float m0 = NEGBIG, m1 = NEGBIG, l0 = 0.f, l1 = 0.f;
    (void)m; (void)l;

    for (int kt = 0; kt < KT; kt++) {
        const int buf = kt & 1;
        asm volatile("cp.async.wait_group 1;");
        __syncthreads();

        float* Kb = Ks0 + buf * 64 * KSTR;
        const float* Vb = Vs0 + buf * 64 * VSTR;

        // --- pre-convert K tile to tf32(rna) in place (whole CTA) ---
        #pragma unroll
        for (int it = 0; it < 8; it++) {
            int c = tid + it * 128;
            int r = c >> 4, p = (c & 15) * 4;
            float4* a = (float4*)(Kb + r * KSTR + p);
            float4 x = *a;
            uint4 y;
            y.x = f2tf(x.x); y.y = f2tf(x.y); y.z = f2tf(x.z); y.w = f2tf(x.w);
            *(uint4*)a = y;
        }
        __syncthreads();

        const bool needmask = (kt >= qt) && ((kt + 1) * BC > bp);

        // ================= HALF A (cols 0..31 of tile) =================
        float SA[4][4];
        #pragma unroll
        for (int i = 0; i < 4; i++) { SA[i][0] = SA[i][1] = SA[i][2] = SA[i][3] = 0.f; }
        #pragma unroll
        for (int ks = 0; ks < 8; ks++) {
            #pragma unroll
            for (int nt = 0; nt < 4; nt++) {
                uint2 kk = *(const uint2*)(Kb + (nt * 8 + g) * KSTR + ks * 8 + 2 * tg);
                mma8(SA[nt], qa[ks][0], qa[ks][1], qa[ks][2], qa[ks][3], kk.x, kk.y);
            }
        }
        if (needmask) {
            #pragma unroll
            for (int nt = 0; nt < 4; nt++) {
                int j0 = kt * BC + nt * 8 + tg * 2;
                if (!(j0     <= r_lo || j0     < bp)) SA[nt][0] = NEGBIG;
                if (!(j0 + 1 <= r_lo || j0 + 1 < bp)) SA[nt][1] = NEGBIG;
                if (!(j0     <= r_hi || j0     < bp)) SA[nt][2] = NEGBIG;
                if (!(j0 + 1 <= r_hi || j0 + 1 < bp)) SA[nt][3] = NEGBIG;
            }
        }
        // max A (shuffle chain — S_B MMAs below fill these stalls)
        float tA0 = NEGBIG, tA1 = NEGBIG;
        #pragma unroll
        for (int nt = 0; nt < 4; nt++) {
            tA0 = fmaxf(tA0, fmaxf(SA[nt][0], SA[nt][1]));
            tA1 = fmaxf(tA1, fmaxf(SA[nt][2], SA[nt][3]));
        }
        tA0 = fmaxf(tA0, __shfl_xor_sync(0xffffffffu, tA0, 1));
        tA0 = fmaxf(tA0, __shfl_xor_sync(0xffffffffu, tA0, 2));
        tA1 = fmaxf(tA1, __shfl_xor_sync(0xffffffffu, tA1, 1));
        tA1 = fmaxf(tA1, __shfl_xor_sync(0xffffffffu, tA1, 2));

        // ========== S for HALF B (independent; overlaps max-A) ==========
        float SB[4][4];
        #pragma unroll
        for (int i = 0; i < 4; i++) { SB[i][0] = SB[i][1] = SB[i][2] = SB[i][3] = 0.f; }
        #pragma unroll
        for (int ks = 0; ks < 8; ks++) {
            #pragma unroll
            for (int nt = 0; nt < 4; nt++) {
                uint2 kk = *(const uint2*)(Kb + ((nt + 4) * 8 + g) * KSTR + ks * 8 + 2 * tg);
                mma8(SB[nt], qa[ks][0], qa[ks][1], qa[ks][2], qa[ks][3], kk.x, kk.y);
            }
        }

        // finish softmax A
        {
            const float mnA0 = fmaxf(m0, tA0), mnA1 = fmaxf(m1, tA1);
            const float rsc0 = ex2(m0 - mnA0), rsc1 = ex2(m1 - mnA1);
            m0 = mnA0; m1 = mnA1;
            float sum0 = 0.f, sum1 = 0.f;
            #pragma unroll
            for (int nt = 0; nt < 4; nt++) {
                SA[nt][0] = ex2(SA[nt][0] - mnA0);
                SA[nt][1] = ex2(SA[nt][1] - mnA0);
                SA[nt][2] = ex2(SA[nt][2] - mnA1);
                SA[nt][3] = ex2(SA[nt][3] - mnA1);
                sum0 += SA[nt][0] + SA[nt][1];
                sum1 += SA[nt][2] + SA[nt][3];
            }
            sum0 += __shfl_xor_sync(0xffffffffu, sum0, 1);
            sum0 += __shfl_xor_sync(0xffffffffu, sum0, 2);
            sum1 += __shfl_xor_sync(0xffffffffu, sum1, 1);
            sum1 += __shfl_xor_sync(0xffffffffu, sum1, 2);
            l0 = l0 * rsc0 + sum0;
            l1 = l1 * rsc1 + sum1;
            #pragma unroll
            for (int nt = 0; nt < 8; nt++) {
                O[nt][0] *= rsc0; O[nt][1] *= rsc0;
                O[nt][2] *= rsc1; O[nt][3] *= rsc1;
            }
        }

        // ---- PV half A : O += P_A V[0:32,:] ----
        #pragma unroll
        for (int ks = 0; ks < 4; ks++) {
            uint32_t a0 = f2tf(SA[ks][0]);
            uint32_t a1 = f2tf(SA[ks][2]);
            uint32_t a2 = f2tf(SA[ks][1]);
            uint32_t a3 = f2tf(SA[ks][3]);
            const float* v0 = Vb + (ks * 8 + 2 * tg) * VSTR + g;
            #pragma unroll
            for (int nt = 0; nt < 8; nt++) {
                uint32_t b0 = __float_as_uint(v0[nt * 8]);
                uint32_t b1 = __float_as_uint(v0[VSTR + nt * 8]);
                mma8(O[nt], a0, a1, a2, a3, b0, b1);
            }
        }

        // ========== softmax B (independent of PV_A; overlaps it) ==========
        if (needmask) {
            #pragma unroll
            for (int nt = 0; nt < 4; nt++) {
                int j0 = kt * BC + 32 + nt * 8 + tg * 2;
                if (!(j0     <= r_lo || j0     < bp)) SB[nt][0] = NEGBIG;
                if (!(j0 + 1 <= r_lo || j0 + 1 < bp)) SB[nt][1] = NEGBIG;
                if (!(j0     <= r_hi || j0     < bp)) SB[nt][2] = NEGBIG;
                if (!(j0 + 1 <= r_hi || j0 + 1 < bp)) SB[nt][3] = NEGBIG;
            }
        }
        {
            float tB0 = NEGBIG, tB1 = NEGBIG;
            #pragma unroll
            for (int nt = 0; nt < 4; nt++) {
                tB0 = fmaxf(tB0, fmaxf(SB[nt][0], SB[nt][1]));
                tB1 = fmaxf(tB1, fmaxf(SB[nt][2], SB[nt][3]));
            }
            tB0 = fmaxf(tB0, __shfl_xor_sync(0xffffffffu, tB0, 1));
            tB0 = fmaxf(tB0, __shfl_xor_sync(0xffffffffu, tB0, 2));
            tB1 = fmaxf(tB1, __shfl_xor_sync(0xffffffffu, tB1, 1));
            tB1 = fmaxf(tB1, __shfl_xor_sync(0xffffffffu, tB1, 2));
            const float mnB0 = fmaxf(m0, tB0), mnB1 = fmaxf(m1, tB1);
            const float rsc0 = ex2(m0 - mnB0), rsc1 = ex2(m1 - mnB1);
            m0 = mnB0; m1 = mnB1;
            float sum0 = 0.f, sum1 = 0.f;
            #pragma unroll
            for (int nt = 0; nt < 4; nt++) {
                SB[nt][0] = ex2(SB[nt][0] - mnB0);
                SB[nt][1] = ex2(SB[nt][1] - mnB0);
                SB[nt][2] = ex2(SB[nt][2] - mnB1);
                SB[nt][3] = ex2(SB[nt][3] - mnB1);
                sum0 += SB[nt][0] + SB[nt][1];
                sum1 += SB[nt][2] + SB[nt][3];
            }
            sum0 += __shfl_xor_sync(0xffffffffu, sum0, 1);
            sum0 += __shfl_xor_sync(0xffffffffu, sum0, 2);
            sum1 += __shfl_xor_sync(0xffffffffu, sum1, 1);
            sum1 += __shfl_xor_sync(0xffffffffu, sum1, 2);
            l0 = l0 * rsc0 + sum0;
            l1 = l1 * rsc1 + sum1;
            #pragma unroll
            for (int nt = 0; nt < 8; nt++) {   // waits on PV_A results (reg dep)
                O[nt][0] *= rsc0; O[nt][1] *= rsc0;
                O[nt][2] *= rsc1; O[nt][3] *= rsc1;
            }
        }

        // ---- PV half B : O += P_B V[32:64,:] ----
        #pragma unroll
        for (int ks = 0; ks < 4; ks++) {
            uint32_t a0 = f2tf(SB[ks][0]);
            uint32_t a1 = f2tf(SB[ks][2]);
            uint32_t a2 = f2tf(SB[ks][1]);
            uint32_t a3 = f2tf(SB[ks][3]);
            const float* v0 = Vb + ((ks + 4) * 8 + 2 * tg) * VSTR + g;
            #pragma unroll
            for (int nt = 0; nt < 8; nt++) {
                uint32_t b0 = __float_as_uint(v0[nt * 8]);
                uint32_t b1 = __float_as_uint(v0[VSTR + nt * 8]);
                mma8(O[nt], a0, a1, a2, a3, b0, b1);
            }
        }

        __syncthreads();              // all warps done with this KV buffer
        issue_kv(kt + 2, buf);        // (empty commit past KT keeps groups aligned)
    }
    asm volatile("cp.async.wait_group 0;");

    // --- normalize + store ---
    const float inv0 = 1.f / l0, inv1 = 1.f / l1;
    #pragma unroll
    for (int nt = 0; nt < 8; nt++) {
        const int d = nt * 8 + tg * 2;
        *(float2*)(ob + (size_t)r_lo * rs + d) = make_float2(O[nt][0] * inv0, O[nt][1] * inv0);
        *(float2*)(ob + (size_t)r_hi * rs + d) = make_float2(O[nt][2] * inv1, O[nt][3] * inv1);
    }
}

extern "C" void kernel_launch(void* const* d_in, const int* in_sizes, int n_in,
                              void* d_out, int out_size) {
    const float* q   = (const float*)d_in[0];
    const float* k   = (const float*)d_in[1];
    const float* v   = (const float*)d_in[2];
    const int*   glm = (const int*)d_in[3];
    const int b   = in_sizes[3];
    const int seq = in_sizes[0] / (b * NHD * HSZ);

    cudaFuncSetAttribute(fa_glm_kernel,
                         cudaFuncAttributeMaxDynamicSharedMemorySize, SMEM_BYTES);
    dim3 grid(seq / BR, NHD, b);
    fa_glm_kernel<<<grid, 128, SMEM_BYTES>>>(q, k, v, glm, (float*)d_out, seq);
}

// round 11
// speedup vs baseline: 1.0259x; 1.0084x over previous
#include <cuda_runtime.h>
#include <cstdint>

// s=2048, nh=16, hs=64, fp32. b from in_sizes.
#define NHD   16
#define HSZ   64
#define BR    64
#define BC    64
#define KSTR  72   // K smem stride: LDS.64 K-frags bank = (8g+2tg) -> conflict-free
#define VSTR  68   // V smem stride: LDS.32 V-frags bank = (8tg+4d+8nt+g) -> conflict-free
#define SM_K  (64 * KSTR)        // single-buffered K
#define SM_V  (2 * 64 * VSTR)    // double-buffered V
#define SMEM_BYTES ((SM_K + SM_V) * 4)   // 53248 B -> 4 CTAs/SM
#define NEGBIG (-1e30f)
#define LOG2E  1.4426950408889634f

__device__ __forceinline__ uint32_t f2tf(float x) {
    uint32_t r;
    asm("cvt.rna.tf32.f32 %0, %1;" : "=r"(r) : "f"(x));
    return r;
}
__device__ __forceinline__ float ex2(float x) {
    float y;
    asm("ex2.approx.f32 %0, %1;" : "=f"(y) : "f"(x));
    return y;
}
__device__ __forceinline__ void mma8(float* d,
                                     uint32_t a0, uint32_t a1, uint32_t a2, uint32_t a3,
                                     uint32_t b0, uint32_t b1) {
    asm volatile(
        "mma.sync.aligned.m16n8k8.row.col.f32.tf32.tf32.f32 "
        "{%0,%1,%2,%3},{%4,%5,%6,%7},{%8,%9},{%0,%1,%2,%3};"
        : "+f"(d[0]), "+f"(d[1]), "+f"(d[2]), "+f"(d[3])
        : "r"(a0), "r"(a1), "r"(a2), "r"(a3), "r"(b0), "r"(b1));
}
__device__ __forceinline__ void cpa16(uint32_t dst, const void* src) {
    asm volatile("cp.async.cg.shared.global [%0], [%1], 16;" :: "r"(dst), "l"(src));
}

// k-permutation sigma(tg)=2tg, sigma(tg+4)=2tg+1 applied consistently to
// (Q,K) for S=QK^T and to (P,V) for O=PV. Under sigma, the S accumulator
// C-fragment (c0,c2,c1,c3) IS the A-fragment of P -> no SMEM repack.
// Single-buffered K (dead after the S-MMAs; mid-tile sync frees it for the
// next tile's cp.async), double-buffered V. 53KB SMEM + 128 regs -> 4 CTAs/SM.
__global__ void __launch_bounds__(128, 4) fa_glm_kernel(
    const float* __restrict__ q, const float* __restrict__ k,
    const float* __restrict__ v, const int* __restrict__ glm,
    float* __restrict__ out, int seq)
{
    extern __shared__ float sm[];
    float* Ks = sm;                 // single K tile
    float* Vs0 = sm + SM_K;         // two V tiles

    // Heavy q-tiles (large qt => more KV tiles) first: better last-wave tail.
    const int qt = gridDim.x - 1 - blockIdx.x;
    const int h = blockIdx.y, bi = blockIdx.z;
    const int tid = threadIdx.x, lane = tid & 31, w = tid >> 5;
    const int g = lane >> 2, tg = lane & 3;

    const int bp   = glm[bi];
    const int iq0  = qt * BR;
    const int kend = max(iq0 + BR, bp);
    const int KT   = (kend + BC - 1) / BC;

    const size_t rs = (size_t)NHD * HSZ;
    const float* qb = q + (size_t)bi * seq * rs + (size_t)h * HSZ;
    const float* kb = k + (size_t)bi * seq * rs + (size_t)h * HSZ;
    const float* vb = v + (size_t)bi * seq * rs + (size_t)h * HSZ;
    float*       ob = out + (size_t)bi * seq * rs + (size_t)h * HSZ;

    // K -> single buffer; V(t) -> buffer t&1. One commit group per tile.
    auto issue_kv = [&](int t) {
        if (t < KT) {
            const float* sk = kb + (size_t)(t * BC) * rs;
            const float* sv = vb + (size_t)(t * BC) * rs;
            uint32_t kd = (uint32_t)__cvta_generic_to_shared(Ks);
            uint32_t vd = (uint32_t)__cvta_generic_to_shared(Vs0 + (t & 1) * 64 * VSTR);
            #pragma unroll
            for (int it = 0; it < 8; it++) {
                int c = tid + it * 128;
                int r = c >> 4, p = (c & 15) * 4;
                cpa16(kd + (r * KSTR + p) * 4, sk + (size_t)r * rs + p);
                cpa16(vd + (r * VSTR + p) * 4, sv + (size_t)r * rs + p);
            }
        }
        asm volatile("cp.async.commit_group;");
    };
    issue_kv(0);

    const int r_lo = iq0 + w * 16 + g;
    const int r_hi = r_lo + 8;

    // --- Q fragments straight from GMEM (permuted k, scale = log2e/8) ---
    uint32_t qa[8][4];
    {
        const float qs = 0.125f * LOG2E;
        const float* q0 = qb + (size_t)r_lo * rs + 2 * tg;
        const float* q1 = qb + (size_t)r_hi * rs + 2 * tg;
        #pragma unroll
        for (int ks = 0; ks < 8; ks++) {
            float2 x0 = *(const float2*)(q0 + ks * 8);
            float2 x1 = *(const float2*)(q1 + ks * 8);
            qa[ks][0] = f2tf(x0.x * qs); qa[ks][2] = f2tf(x0.y * qs);
            qa[ks][1] = f2tf(x1.x * qs); qa[ks][3] = f2tf(x1.y * qs);
        }
    }

    float O[8][4];
    #pragma unroll
    for (int i = 0; i < 8; i++) { O[i][0] = O[i][1] = O[i][2] = O[i][3] = 0.f; }
    float m0 = NEGBIG, m1 = NEGBIG, l0 = 0.f, l1 = 0.f;

    for (int kt = 0; kt < KT; kt++) {
        asm volatile("cp.async.wait_group 0;");
        __syncthreads();                            // KV(kt) visible to all

        const float* Vb = Vs0 + (kt & 1) * 64 * VSTR;
        const bool needmask = (kt >= qt) && ((kt + 1) * BC > bp);

        // ================= S: HALF A (cols 0..31), inline rna cvt ========
        float SA[4][4];
        #pragma unroll
        for (int i = 0; i < 4; i++) { SA[i][0] = SA[i][1] = SA[i][2] = SA[i][3] = 0.f; }
        #pragma unroll
        for (int ks = 0; ks < 8; ks++) {
            #pragma unroll
            for (int nt = 0; nt < 4; nt++) {
                float2 kk = *(const float2*)(Ks + (nt * 8 + g) * KSTR + ks * 8 + 2 * tg);
                mma8(SA[nt], qa[ks][0], qa[ks][1], qa[ks][2], qa[ks][3],
                     f2tf(kk.x), f2tf(kk.y));
            }
        }
        if (needmask) {
            #pragma unroll
            for (int nt = 0; nt < 4; nt++) {
                int j0 = kt * BC + nt * 8 + tg * 2;
                if (!(j0     <= r_lo || j0     < bp)) SA[nt][0] = NEGBIG;
                if (!(j0 + 1 <= r_lo || j0 + 1 < bp)) SA[nt][1] = NEGBIG;
                if (!(j0     <= r_hi || j0     < bp)) SA[nt][2] = NEGBIG;
                if (!(j0 + 1 <= r_hi || j0 + 1 < bp)) SA[nt][3] = NEGBIG;
            }
        }
        // max A (shuffle chain — S_B MMAs below fill these stalls)
        float tA0 = NEGBIG, tA1 = NEGBIG;
        #pragma unroll
        for (int nt = 0; nt < 4; nt++) {
            tA0 = fmaxf(tA0, fmaxf(SA[nt][0], SA[nt][1]));
            tA1 = fmaxf(tA1, fmaxf(SA[nt][2], SA[nt][3]));
        }
        tA0 = fmaxf(tA0, __shfl_xor_sync(0xffffffffu, tA0, 1));
        tA0 = fmaxf(tA0, __shfl_xor_sync(0xffffffffu, tA0, 2));
        tA1 = fmaxf(tA1, __shfl_xor_sync(0xffffffffu, tA1, 1));
        tA1 = fmaxf(tA1, __shfl_xor_sync(0xffffffffu, tA1, 2));

        // ========== S: HALF B (independent; overlaps max-A) ==========
        float SB[4][4];
        #pragma unroll
        for (int i = 0; i < 4; i++) { SB[i][0] = SB[i][1] = SB[i][2] = SB[i][3] = 0.f; }
        #pragma unroll
        for (int ks = 0; ks < 8; ks++) {
            #pragma unroll
            for (int nt = 0; nt < 4; nt++) {
                float2 kk = *(const float2*)(Ks + ((nt + 4) * 8 + g) * KSTR + ks * 8 + 2 * tg);
                mma8(SB[nt], qa[ks][0], qa[ks][1], qa[ks][2], qa[ks][3],
                     f2tf(kk.x), f2tf(kk.y));
            }
        }

        // K buffer now dead for all warps -> refill it for kt+1.
        __syncthreads();
        issue_kv(kt + 1);

        // finish softmax A
        {
            const float mnA0 = fmaxf(m0, tA0), mnA1 = fmaxf(m1, tA1);
            const float rsc0 = ex2(m0 - mnA0), rsc1 = ex2(m1 - mnA1);
            m0 = mnA0; m1 = mnA1;
            float sum0 = 0.f, sum1 = 0.f;
            #pragma unroll
            for (int nt = 0; nt < 4; nt++) {
                SA[nt][0] = ex2(SA[nt][0] - mnA0);
                SA[nt][1] = ex2(SA[nt][1] - mnA0);
                SA[nt][2] = ex2(SA[nt][2] - mnA1);
                SA[nt][3] = ex2(SA[nt][3] - mnA1);
                sum0 += SA[nt][0] + SA[nt][1];
                sum1 += SA[nt][2] + SA[nt][3];
            }
            sum0 += __shfl_xor_sync(0xffffffffu, sum0, 1);
            sum0 += __shfl_xor_sync(0xffffffffu, sum0, 2);
            sum1 += __shfl_xor_sync(0xffffffffu, sum1, 1);
            sum1 += __shfl_xor_sync(0xffffffffu, sum1, 2);
            l0 = l0 * rsc0 + sum0;
            l1 = l1 * rsc1 + sum1;
            #pragma unroll
            for (int nt = 0; nt < 8; nt++) {
                O[nt][0] *= rsc0; O[nt][1] *= rsc0;
                O[nt][2] *= rsc1; O[nt][3] *= rsc1;
            }
        }

        // ---- PV half A : O += P_A V[0:32,:] ----
        #pragma unroll
        for (int ks = 0; ks < 4; ks++) {
            uint32_t a0 = f2tf(SA[ks][0]);
            uint32_t a1 = f2tf(SA[ks][2]);
            uint32_t a2 = f2tf(SA[ks][1]);
            uint32_t a3 = f2tf(SA[ks][3]);
            const float* v0 = Vb + (ks * 8 + 2 * tg) * VSTR + g;
            #pragma unroll
            for (int nt = 0; nt < 8; nt++) {
                uint32_t b0 = __float_as_uint(v0[nt * 8]);
                uint32_t b1 = __float_as_uint(v0[VSTR + nt * 8]);
                mma8(O[nt], a0, a1, a2, a3, b0, b1);
            }
        }

        // ========== softmax B (independent of PV_A; overlaps it) ==========
        if (needmask) {
            #pragma unroll
            for (int nt = 0; nt < 4; nt++) {
                int j0 = kt * BC + 32 + nt * 8 + tg * 2;
                if (!(j0     <= r_lo || j0     < bp)) SB[nt][0] = NEGBIG;
                if (!(j0 + 1 <= r_lo || j0 + 1 < bp)) SB[nt][1] = NEGBIG;
                if (!(j0     <= r_hi || j0     < bp)) SB[nt][2] = NEGBIG;
                if (!(j0 + 1 <= r_hi || j0 + 1 < bp)) SB[nt][3] = NEGBIG;
            }
        }
        {
            float tB0 = NEGBIG, tB1 = NEGBIG;
            #pragma unroll
            for (int nt = 0; nt < 4; nt++) {
                tB0 = fmaxf(tB0, fmaxf(SB[nt][0], SB[nt][1]));
                tB1 = fmaxf(tB1, fmaxf(SB[nt][2], SB[nt][3]));
            }
            tB0 = fmaxf(tB0, __shfl_xor_sync(0xffffffffu, tB0, 1));
            tB0 = fmaxf(tB0, __shfl_xor_sync(0xffffffffu, tB0, 2));
            tB1 = fmaxf(tB1, __shfl_xor_sync(0xffffffffu, tB1, 1));
            tB1 = fmaxf(tB1, __shfl_xor_sync(0xffffffffu, tB1, 2));
            const float mnB0 = fmaxf(m0, tB0), mnB1 = fmaxf(m1, tB1);
            const float rsc0 = ex2(m0 - mnB0), rsc1 = ex2(m1 - mnB1);
            m0 = mnB0; m1 = mnB1;
            float sum0 = 0.f, sum1 = 0.f;
            #pragma unroll
            for (int nt = 0; nt < 4; nt++) {
                SB[nt][0] = ex2(SB[nt][0] - mnB0);
                SB[nt][1] = ex2(SB[nt][1] - mnB0);
                SB[nt][2] = ex2(SB[nt][2] - mnB1);
                SB[nt][3] = ex2(SB[nt][3] - mnB1);
                sum0 += SB[nt][0] + SB[nt][1];
                sum1 += SB[nt][2] + SB[nt][3];
            }
            sum0 += __shfl_xor_sync(0xffffffffu, sum0, 1);
            sum0 += __shfl_xor_sync(0xffffffffu, sum0, 2);
            sum1 += __shfl_xor_sync(0xffffffffu, sum1, 1);
            sum1 += __shfl_xor_sync(0xffffffffu, sum1, 2);
            l0 = l0 * rsc0 + sum0;
            l1 = l1 * rsc1 + sum1;
            #pragma unroll
            for (int nt = 0; nt < 8; nt++) {   // waits on PV_A results (reg dep)
                O[nt][0] *= rsc0; O[nt][1] *= rsc0;
                O[nt][2] *= rsc1; O[nt][3] *= rsc1;
            }
        }

        // ---- PV half B : O += P_B V[32:64,:] ----
        #pragma unroll
        for (int ks = 0; ks < 4; ks++) {
            uint32_t a0 = f2tf(SB[ks][0]);
            uint32_t a1 = f2tf(SB[ks][2]);
            uint32_t a2 = f2tf(SB[ks][1]);
            uint32_t a3 = f2tf(SB[ks][3]);
            const float* v0 = Vb + ((ks + 4) * 8 + 2 * tg) * VSTR + g;
            #pragma unroll
            for (int nt = 0; nt < 8; nt++) {
                uint32_t b0 = __float_as_uint(v0[nt * 8]);
                uint32_t b1 = __float_as_uint(v0[VSTR + nt * 8]);
                mma8(O[nt], a0, a1, a2, a3, b0, b1);
            }
        }
        // no end-of-tile barrier: next tile's top sync orders V reuse,
        // and K refill was already ordered by the mid-tile sync.
    }
    asm volatile("cp.async.wait_group 0;");

    // --- normalize + store ---
    const float inv0 = 1.f / l0, inv1 = 1.f / l1;
    #pragma unroll
    for (int nt = 0; nt < 8; nt++) {
        const int d = nt * 8 + tg * 2;
        *(float2*)(ob + (size_t)r_lo * rs + d) = make_float2(O[nt][0] * inv0, O[nt][1] * inv0);
        *(float2*)(ob + (size_t)r_hi * rs + d) = make_float2(O[nt][2] * inv1, O[nt][3] * inv1);
    }
}

extern "C" void kernel_launch(void* const* d_in, const int* in_sizes, int n_in,
                              void* d_out, int out_size) {
    const float* q   = (const float*)d_in[0];
    const float* k   = (const float*)d_in[1];
    const float* v   = (const float*)d_in[2];
    const int*   glm = (const int*)d_in[3];
    const int b   = in_sizes[3];
    const int seq = in_sizes[0] / (b * NHD * HSZ);

    cudaFuncSetAttribute(fa_glm_kernel,
                         cudaFuncAttributeMaxDynamicSharedMemorySize, SMEM_BYTES);
    dim3 grid(seq / BR, NHD, b);
    fa_glm_kernel<<<grid, 128, SMEM_BYTES>>>(q, k, v, glm, (float*)d_out, seq);
}

// round 12
// speedup vs baseline: 1.2122x; 1.1815x over previous
#include <cuda_runtime.h>
#include <cstdint>

// s=2048, nh=16, hs=64, fp32 io. b from in_sizes.
#define NHD   16
#define HSZ   64
#define BR    64
#define BC    64
#define KF_STR  68            // fp32 K staging stride (floats)
#define KH_STRW 36            // fp16 K tile row stride in 32-bit words (72 fp16)
#define VSTR    68            // fp32 V stride (floats): PV frag banks 8tg+g -> clean
#define KF_BYTES (64 * KF_STR * 4)          // 17408
#define KH_BYTES (64 * KH_STRW * 4)         //  9216
#define V_BYTES  (64 * VSTR * 4)            // 17408
#define SMEM_BYTES (KF_BYTES + KH_BYTES + 2 * V_BYTES)   // 61440 -> 3 CTAs/SM
#define NEGBIG (-1e30f)
#define LOG2E  1.4426950408889634f

__device__ __forceinline__ uint32_t packh2(float lo, float hi) {
    uint32_t r;
    asm("cvt.rn.f16x2.f32 %0, %2, %1;" : "=r"(r) : "f"(lo), "f"(hi));
    return r;
}
__device__ __forceinline__ float ex2(float x) {
    float y;
    asm("ex2.approx.f32 %0, %1;" : "=f"(y) : "f"(x));
    return y;
}
// fp16 m16n8k16, fp32 accumulate. A row-major, B col-major.
__device__ __forceinline__ void mma16(float* d,
                                      uint32_t a0, uint32_t a1, uint32_t a2, uint32_t a3,
                                      uint32_t b0, uint32_t b1) {
    asm volatile(
        "mma.sync.aligned.m16n8k16.row.col.f32.f16.f16.f32 "
        "{%0,%1,%2,%3},{%4,%5,%6,%7},{%8,%9},{%0,%1,%2,%3};"
        : "+f"(d[0]), "+f"(d[1]), "+f"(d[2]), "+f"(d[3])
        : "r"(a0), "r"(a1), "r"(a2), "r"(a3), "r"(b0), "r"(b1));
}
__device__ __forceinline__ void cpa16(uint32_t dst, const void* src) {
    asm volatile("cp.async.cg.shared.global [%0], [%1], 16;" :: "r"(dst), "l"(src));
}

// fp16 m16n8k16 path. Fragment facts used:
//  A-frag: a0={A[g][2tg,2tg+1]} a1={A[g+8][..]} a2={A[g][2tg+8,+9]} a3={A[g+8][..]}
//  B-frag: b0={B[2tg][g],B[2tg+1][g]} b1={B[2tg+8][g],B[2tg+9][g]}
//  C-frag: c0=(g,2tg) c1=(g,2tg+1) c2=(g+8,2tg) c3=(g+8,2tg+1)
// => PV A-frag of P is register packing of the S accumulators (no repack pass),
//    K b-frags are two conflict-free LDS.32 from the fp16 K tile,
//    V b-frags are two fp32 LDS.32 + one cvt pack.
__global__ void __launch_bounds__(128, 3) fa_glm_kernel(
    const float* __restrict__ q, const float* __restrict__ k,
    const float* __restrict__ v, const int* __restrict__ glm,
    float* __restrict__ out, int seq)
{
    extern __shared__ char smb[];
    float*    KF  = (float*)smb;                       // fp32 K staging (single)
    uint32_t* KH  = (uint32_t*)(smb + KF_BYTES);       // fp16 K tile (single)
    float*    Vs0 = (float*)(smb + KF_BYTES + KH_BYTES); // fp32 V (double)

    // Heavy q-tiles first: better last-wave tail.
    const int qt = gridDim.x - 1 - blockIdx.x;
    const int h = blockIdx.y, bi = blockIdx.z;
    const int tid = threadIdx.x, lane = tid & 31, w = tid >> 5;
    const int g = lane >> 2, tg = lane & 3;

    const int bp   = glm[bi];
    const int iq0  = qt * BR;
    const int kend = max(iq0 + BR, bp);
    const int KT   = (kend + BC - 1) / BC;

    const size_t rs = (size_t)NHD * HSZ;
    const float* qb = q + (size_t)bi * seq * rs + (size_t)h * HSZ;
    const float* kb = k + (size_t)bi * seq * rs + (size_t)h * HSZ;
    const float* vb = v + (size_t)bi * seq * rs + (size_t)h * HSZ;
    float*       ob = out + (size_t)bi * seq * rs + (size_t)h * HSZ;

    // K(t) -> KF staging; V(t) -> buffer t&1. One commit group per tile.
    auto issue_kv = [&](int t) {
        if (t < KT) {
            const float* sk = kb + (size_t)(t * BC) * rs;
            const float* sv = vb + (size_t)(t * BC) * rs;
            uint32_t kd = (uint32_t)__cvta_generic_to_shared(KF);
            uint32_t vd = (uint32_t)__cvta_generic_to_shared(Vs0 + (t & 1) * 64 * VSTR);
            #pragma unroll
            for (int it = 0; it < 8; it++) {
                int c = tid + it * 128;
                int r = c >> 4, p = (c & 15) * 4;
                cpa16(kd + (r * KF_STR + p) * 4, sk + (size_t)r * rs + p);
                cpa16(vd + (r * VSTR + p) * 4, sv + (size_t)r * rs + p);
            }
        }
        asm volatile("cp.async.commit_group;");
    };
    issue_kv(0);

    const int r_lo = iq0 + w * 16 + g;
    const int r_hi = r_lo + 8;

    // --- Q fragments (fp16 packed) straight from GMEM, scale = log2e/8 ---
    uint32_t qa[4][4];
    {
        const float qs = 0.125f * LOG2E;
        const float* q0 = qb + (size_t)r_lo * rs + 2 * tg;
        const float* q1 = qb + (size_t)r_hi * rs + 2 * tg;
        #pragma unroll
        for (int s = 0; s < 4; s++) {
            float2 x0 = *(const float2*)(q0 + s * 16);
            float2 x1 = *(const float2*)(q0 + s * 16 + 8);
            float2 y0 = *(const float2*)(q1 + s * 16);
            float2 y1 = *(const float2*)(q1 + s * 16 + 8);
            qa[s][0] = packh2(x0.x * qs, x0.y * qs);
            qa[s][1] = packh2(y0.x * qs, y0.y * qs);
            qa[s][2] = packh2(x1.x * qs, x1.y * qs);
            qa[s][3] = packh2(y1.x * qs, y1.y * qs);
        }
    }

    float O[8][4];
    #pragma unroll
    for (int i = 0; i < 8; i++) { O[i][0] = O[i][1] = O[i][2] = O[i][3] = 0.f; }
    float m0 = NEGBIG, m1 = NEGBIG, l0 = 0.f, l1 = 0.f;

    for (int kt = 0; kt < KT; kt++) {
        asm volatile("cp.async.wait_group 0;");
        __syncthreads();                       // K(t),V(t) landed; KH(t-1) consumed

        // --- convert K staging fp32 -> fp16 tile (CTA-wide, once per tile) ---
        #pragma unroll
        for (int it = 0; it < 8; it++) {
            int c = tid + it * 128;
            int r = c >> 4, p = (c & 15) * 4;
            float4 x = *(const float4*)(KF + r * KF_STR + p);
            KH[r * KH_STRW + p / 2]     = packh2(x.x, x.y);
            KH[r * KH_STRW + p / 2 + 1] = packh2(x.z, x.w);
        }
        __syncthreads();                       // KH visible, KF free
        issue_kv(kt + 1);                      // next tile's loads start now

        const float* Vb = Vs0 + (kt & 1) * 64 * VSTR;
        const bool needmask = (kt >= qt) && ((kt + 1) * BC > bp);

        // ================= S: HALF A (cols 0..31) =================
        float SA[4][4];
        #pragma unroll
        for (int i = 0; i < 4; i++) { SA[i][0] = SA[i][1] = SA[i][2] = SA[i][3] = 0.f; }
        #pragma unroll
        for (int s = 0; s < 4; s++) {
            #pragma unroll
            for (int nt = 0; nt < 4; nt++) {
                const uint32_t* kw = KH + (nt * 8 + g) * KH_STRW + s * 8 + tg;
                mma16(SA[nt], qa[s][0], qa[s][1], qa[s][2], qa[s][3], kw[0], kw[4]);
            }
        }
        if (needmask) {
            #pragma unroll
            for (int nt = 0; nt < 4; nt++) {
                int j0 = kt * BC + nt * 8 + tg * 2;
                if (!(j0     <= r_lo || j0     < bp)) SA[nt][0] = NEGBIG;
                if (!(j0 + 1 <= r_lo || j0 + 1 < bp)) SA[nt][1] = NEGBIG;
                if (!(j0     <= r_hi || j0     < bp)) SA[nt][2] = NEGBIG;
                if (!(j0 + 1 <= r_hi || j0 + 1 < bp)) SA[nt][3] = NEGBIG;
            }
        }
        // max A (shuffles overlap with S-half-B MMAs below)
        float tA0 = NEGBIG, tA1 = NEGBIG;
        #pragma unroll
        for (int nt = 0; nt < 4; nt++) {
            tA0 = fmaxf(tA0, fmaxf(SA[nt][0], SA[nt][1]));
            tA1 = fmaxf(tA1, fmaxf(SA[nt][2], SA[nt][3]));
        }
        tA0 = fmaxf(tA0, __shfl_xor_sync(0xffffffffu, tA0, 1));
        tA0 = fmaxf(tA0, __shfl_xor_sync(0xffffffffu, tA0, 2));
        tA1 = fmaxf(tA1, __shfl_xor_sync(0xffffffffu, tA1, 1));
        tA1 = fmaxf(tA1, __shfl_xor_sync(0xffffffffu, tA1, 2));

        // ========== S: HALF B (independent; overlaps max-A) ==========
        float SB[4][4];
        #pragma unroll
        for (int i = 0; i < 4; i++) { SB[i][0] = SB[i][1] = SB[i][2] = SB[i][3] = 0.f; }
        #pragma unroll
        for (int s = 0; s < 4; s++) {
            #pragma unroll
            for (int nt = 0; nt < 4; nt++) {
                const uint32_t* kw = KH + ((nt + 4) * 8 + g) * KH_STRW + s * 8 + tg;
                mma16(SB[nt], qa[s][0], qa[s][1], qa[s][2], qa[s][3], kw[0], kw[4]);
            }
        }

        // finish softmax A
        {
            const float mnA0 = fmaxf(m0, tA0), mnA1 = fmaxf(m1, tA1);
            const float rsc0 = ex2(m0 - mnA0), rsc1 = ex2(m1 - mnA1);
            m0 = mnA0; m1 = mnA1;
            float sum0 = 0.f, sum1 = 0.f;
            #pragma unroll
            for (int nt = 0; nt < 4; nt++) {
                SA[nt][0] = ex2(SA[nt][0] - mnA0);
                SA[nt][1] = ex2(SA[nt][1] - mnA0);
                SA[nt][2] = ex2(SA[nt][2] - mnA1);
                SA[nt][3] = ex2(SA[nt][3] - mnA1);
                sum0 += SA[nt][0] + SA[nt][1];
                sum1 += SA[nt][2] + SA[nt][3];
            }
            sum0 += __shfl_xor_sync(0xffffffffu, sum0, 1);
            sum0 += __shfl_xor_sync(0xffffffffu, sum0, 2);
            sum1 += __shfl_xor_sync(0xffffffffu, sum1, 1);
            sum1 += __shfl_xor_sync(0xffffffffu, sum1, 2);
            l0 = l0 * rsc0 + sum0;
            l1 = l1 * rsc1 + sum1;
            #pragma unroll
            for (int nt = 0; nt < 8; nt++) {
                O[nt][0] *= rsc0; O[nt][1] *= rsc0;
                O[nt][2] *= rsc1; O[nt][3] *= rsc1;
            }
        }

        // ---- PV half A : O += P_A V[0:32,:]  (P packed from S accums) ----
        #pragma unroll
        for (int s2 = 0; s2 < 2; s2++) {
            uint32_t a0 = packh2(SA[2 * s2][0],     SA[2 * s2][1]);
            uint32_t a1 = packh2(SA[2 * s2][2],     SA[2 * s2][3]);
            uint32_t a2 = packh2(SA[2 * s2 + 1][0], SA[2 * s2 + 1][1]);
            uint32_t a3 = packh2(SA[2 * s2 + 1][2], SA[2 * s2 + 1][3]);
            const float* vr = Vb + (s2 * 16 + 2 * tg) * VSTR;
            #pragma unroll
            for (int nt = 0; nt < 8; nt++) {
                int n = nt * 8 + g;
                uint32_t b0 = packh2(vr[n],            vr[VSTR + n]);
                uint32_t b1 = packh2(vr[8 * VSTR + n], vr[9 * VSTR + n]);
                mma16(O[nt], a0, a1, a2, a3, b0, b1);
            }
        }

        // ========== softmax B (independent of PV_A; overlaps it) ==========
        if (needmask) {
            #pragma unroll
            for (int nt = 0; nt < 4; nt++) {
                int j0 = kt * BC + 32 + nt * 8 + tg * 2;
                if (!(j0     <= r_lo || j0     < bp)) SB[nt][0] = NEGBIG;
                if (!(j0 + 1 <= r_lo || j0 + 1 < bp)) SB[nt][1] = NEGBIG;
                if (!(j0     <= r_hi || j0     < bp)) SB[nt][2] = NEGBIG;
                if (!(j0 + 1 <= r_hi || j0 + 1 < bp)) SB[nt][3] = NEGBIG;
            }
        }
        {
            float tB0 = NEGBIG, tB1 = NEGBIG;
            #pragma unroll
            for (int nt = 0; nt < 4; nt++) {
                tB0 = fmaxf(tB0, fmaxf(SB[nt][0], SB[nt][1]));
                tB1 = fmaxf(tB1, fmaxf(SB[nt][2], SB[nt][3]));
            }
            tB0 = fmaxf(tB0, __shfl_xor_sync(0xffffffffu, tB0, 1));
            tB0 = fmaxf(tB0, __shfl_xor_sync(0xffffffffu, tB0, 2));
            tB1 = fmaxf(tB1, __shfl_xor_sync(0xffffffffu, tB1, 1));
            tB1 = fmaxf(tB1, __shfl_xor_sync(0xffffffffu, tB1, 2));
            const float mnB0 = fmaxf(m0, tB0), mnB1 = fmaxf(m1, tB1);
            const float rsc0 = ex2(m0 - mnB0), rsc1 = ex2(m1 - mnB1);
            m0 = mnB0; m1 = mnB1;
            float sum0 = 0.f, sum1 = 0.f;
            #pragma unroll
            for (int nt = 0; nt < 4; nt++) {
                SB[nt][0] = ex2(SB[nt][0] - mnB0);
                SB[nt][1] = ex2(SB[nt][1] - mnB0);
                SB[nt][2] = ex2(SB[nt][2] - mnB1);
                SB[nt][3] = ex2(SB[nt][3] - mnB1);
                sum0 += SB[nt][0] + SB[nt][1];
                sum1 += SB[nt][2] + SB[nt][3];
            }
            sum0 += __shfl_xor_sync(0xffffffffu, sum0, 1);
            sum0 += __shfl_xor_sync(0xffffffffu, sum0, 2);
            sum1 += __shfl_xor_sync(0xffffffffu, sum1, 1);
            sum1 += __shfl_xor_sync(0xffffffffu, sum1, 2);
            l0 = l0 * rsc0 + sum0;
            l1 = l1 * rsc1 + sum1;
            #pragma unroll
            for (int nt = 0; nt < 8; nt++) {   // waits on PV_A results (reg dep)
                O[nt][0] *= rsc0; O[nt][1] *= rsc0;
                O[nt][2] *= rsc1; O[nt][3] *= rsc1;
            }
        }

        // ---- PV half B : O += P_B V[32:64,:] ----
        #pragma unroll
        for (int s2 = 0; s2 < 2; s2++) {
            uint32_t a0 = packh2(SB[2 * s2][0],     SB[2 * s2][1]);
            uint32_t a1 = packh2(SB[2 * s2][2],     SB[2 * s2][3]);
            uint32_t a2 = packh2(SB[2 * s2 + 1][0], SB[2 * s2 + 1][1]);
            uint32_t a3 = packh2(SB[2 * s2 + 1][2], SB[2 * s2 + 1][3]);
            const float* vr = Vb + ((s2 + 2) * 16 + 2 * tg) * VSTR;
            #pragma unroll
            for (int nt = 0; nt < 8; nt++) {
                int n = nt * 8 + g;
                uint32_t b0 = packh2(vr[n],            vr[VSTR + n]);
                uint32_t b1 = packh2(vr[8 * VSTR + n], vr[9 * VSTR + n]);
                mma16(O[nt], a0, a1, a2, a3, b0, b1);
            }
        }
        // no end barrier: next tile's top sync orders KH/V reuse.
    }
    asm volatile("cp.async.wait_group 0;");

    // --- normalize + store ---
    const float inv0 = 1.f / l0, inv1 = 1.f / l1;
    #pragma unroll
    for (int nt = 0; nt < 8; nt++) {
        const int d = nt * 8 + tg * 2;
        *(float2*)(ob + (size_t)r_lo * rs + d) = make_float2(O[nt][0] * inv0, O[nt][1] * inv0);
        *(float2*)(ob + (size_t)r_hi * rs + d) = make_float2(O[nt][2] * inv1, O[nt][3] * inv1);
    }
}

extern "C" void kernel_launch(void* const* d_in, const int* in_sizes, int n_in,
                              void* d_out, int out_size) {
    const float* q   = (const float*)d_in[0];
    const float* k   = (const float*)d_in[1];
    const float* v   = (const float*)d_in[2];
    const int*   glm = (const int*)d_in[3];
    const int b   = in_sizes[3];
    const int seq = in_sizes[0] / (b * NHD * HSZ);

    cudaFuncSetAttribute(fa_glm_kernel,
                         cudaFuncAttributeMaxDynamicSharedMemorySize, SMEM_BYTES);
    dim3 grid(seq / BR, NHD, b);
    fa_glm_kernel<<<grid, 128, SMEM_BYTES>>>(q, k, v, glm, (float*)d_out, seq);
}